// round 1
// baseline (speedup 1.0000x reference)
#include <cuda_runtime.h>
#include <cstdint>

// Accumulators in device globals (no allocation allowed).
__device__ double g_pos_sum;
__device__ double g_neg_sum;
__device__ unsigned long long g_pos_cnt;

__global__ void init_kernel() {
    g_pos_sum = 0.0;
    g_neg_sum = 0.0;
    g_pos_cnt = 0ull;
}

// Stable softplus(s) = max(s,0) + log1p(exp(-|s|))
__device__ __forceinline__ float softplus_stable(float s) {
    return fmaxf(s, 0.0f) + log1pf(__expf(-fabsf(s)));
}

__global__ void __launch_bounds__(256)
reduce_kernel(const float4* __restrict__ p4,
              const int4*   __restrict__ t4,
              int n4) {
    float lpos = 0.0f, lneg = 0.0f;
    int   lcnt = 0;

    const int stride = gridDim.x * blockDim.x;
    for (int i = blockIdx.x * blockDim.x + threadIdx.x; i < n4; i += stride) {
        float4 p = __ldg(p4 + i);
        int4   t = __ldg(t4 + i);

        // Branchless: true_y is guaranteed 0 or 1.
        {
            bool ip = (t.x != 0);
            float s = ip ? -p.x : p.x;
            float v = softplus_stable(s);
            lpos += ip ? v : 0.0f;
            lneg += ip ? 0.0f : v;
            lcnt += t.x;
        }
        {
            bool ip = (t.y != 0);
            float s = ip ? -p.y : p.y;
            float v = softplus_stable(s);
            lpos += ip ? v : 0.0f;
            lneg += ip ? 0.0f : v;
            lcnt += t.y;
        }
        {
            bool ip = (t.z != 0);
            float s = ip ? -p.z : p.z;
            float v = softplus_stable(s);
            lpos += ip ? v : 0.0f;
            lneg += ip ? 0.0f : v;
            lcnt += t.z;
        }
        {
            bool ip = (t.w != 0);
            float s = ip ? -p.w : p.w;
            float v = softplus_stable(s);
            lpos += ip ? v : 0.0f;
            lneg += ip ? 0.0f : v;
            lcnt += t.w;
        }
    }

    // Warp reduction
    #pragma unroll
    for (int o = 16; o > 0; o >>= 1) {
        lpos += __shfl_down_sync(0xFFFFFFFFu, lpos, o);
        lneg += __shfl_down_sync(0xFFFFFFFFu, lneg, o);
        lcnt += __shfl_down_sync(0xFFFFFFFFu, lcnt, o);
    }

    __shared__ float sp[8];
    __shared__ float sn[8];
    __shared__ int   sc[8];
    int warp = threadIdx.x >> 5;
    if ((threadIdx.x & 31) == 0) {
        sp[warp] = lpos; sn[warp] = lneg; sc[warp] = lcnt;
    }
    __syncthreads();

    if (threadIdx.x == 0) {
        float tp = 0.0f, tn = 0.0f;
        int   tc = 0;
        #pragma unroll
        for (int w = 0; w < 8; w++) { tp += sp[w]; tn += sn[w]; tc += sc[w]; }
        atomicAdd(&g_pos_sum, (double)tp);
        atomicAdd(&g_neg_sum, (double)tn);
        atomicAdd(&g_pos_cnt, (unsigned long long)tc);
    }
}

__global__ void finalize_kernel(float* out, long long total) {
    double npos = (double)g_pos_cnt;
    double nneg = (double)total - npos;
    out[0] = (float)(g_pos_sum / npos + g_neg_sum / nneg);
}

extern "C" void kernel_launch(void* const* d_in, const int* in_sizes, int n_in,
                              void* d_out, int out_size) {
    const float* pred = (const float*)d_in[0];
    const int*   ty   = (const int*)d_in[1];
    float* out = (float*)d_out;

    long long n = (long long)in_sizes[0];   // 8192*8192 = 67108864, divisible by 4
    int n4 = (int)(n / 4);

    init_kernel<<<1, 1>>>();

    const int threads = 256;
    int blocks = 148 * 8;  // grid-stride; ~8 CTAs/SM of work
    reduce_kernel<<<blocks, threads>>>((const float4*)pred, (const int4*)ty, n4);

    finalize_kernel<<<1, 1>>>(out, n);
}

// round 2
// speedup vs baseline: 1.3413x; 1.3413x over previous
#include <cuda_runtime.h>
#include <cstdint>

#define NBLOCKS   592          // 148 SMs * 4 CTAs
#define NTHREADS  256
#define UNROLL    4

// Per-block partials: every slot is overwritten on every call -> no init
// kernel, no atomics, deterministic.
__device__ float g_pos[NBLOCKS];
__device__ float g_neg[NBLOCKS];
__device__ int   g_cnt[NBLOCKS];

__device__ __forceinline__ float softplus_fast(float s) {
    // softplus(s) = max(s,0) + log(1 + exp(-|s|)); __expf/__logf are MUFU-based.
    return fmaxf(s, 0.0f) + __logf(1.0f + __expf(-fabsf(s)));
}

__device__ __forceinline__ void accum(float4 p, int4 t,
                                      float& lpos, float& lneg, int& lcnt) {
    {
        bool ip = (t.x != 0);
        float v = softplus_fast(ip ? -p.x : p.x);
        lpos += ip ? v : 0.0f;  lneg += ip ? 0.0f : v;  lcnt += t.x;
    }
    {
        bool ip = (t.y != 0);
        float v = softplus_fast(ip ? -p.y : p.y);
        lpos += ip ? v : 0.0f;  lneg += ip ? 0.0f : v;  lcnt += t.y;
    }
    {
        bool ip = (t.z != 0);
        float v = softplus_fast(ip ? -p.z : p.z);
        lpos += ip ? v : 0.0f;  lneg += ip ? 0.0f : v;  lcnt += t.z;
    }
    {
        bool ip = (t.w != 0);
        float v = softplus_fast(ip ? -p.w : p.w);
        lpos += ip ? v : 0.0f;  lneg += ip ? 0.0f : v;  lcnt += t.w;
    }
}

__global__ void __launch_bounds__(NTHREADS, 4)
reduce_kernel(const float4* __restrict__ p4,
              const int4*   __restrict__ t4,
              int n4) {
    float lpos = 0.0f, lneg = 0.0f;
    int   lcnt = 0;

    const int stride = gridDim.x * blockDim.x;
    int i = blockIdx.x * blockDim.x + threadIdx.x;

    // Main unrolled loop: 8 independent LDG.128 issued back-to-back.
    for (; i + (UNROLL - 1) * stride < n4; i += UNROLL * stride) {
        float4 p[UNROLL];
        int4   t[UNROLL];
        #pragma unroll
        for (int j = 0; j < UNROLL; j++) p[j] = __ldcs(p4 + i + j * stride);
        #pragma unroll
        for (int j = 0; j < UNROLL; j++) t[j] = __ldcs(t4 + i + j * stride);
        #pragma unroll
        for (int j = 0; j < UNROLL; j++) accum(p[j], t[j], lpos, lneg, lcnt);
    }
    // Remainder
    for (; i < n4; i += stride) {
        accum(__ldcs(p4 + i), __ldcs(t4 + i), lpos, lneg, lcnt);
    }

    // Warp reduction
    #pragma unroll
    for (int o = 16; o > 0; o >>= 1) {
        lpos += __shfl_down_sync(0xFFFFFFFFu, lpos, o);
        lneg += __shfl_down_sync(0xFFFFFFFFu, lneg, o);
        lcnt += __shfl_down_sync(0xFFFFFFFFu, lcnt, o);
    }

    __shared__ float sp[8];
    __shared__ float sn[8];
    __shared__ int   sc[8];
    int warp = threadIdx.x >> 5;
    if ((threadIdx.x & 31) == 0) { sp[warp] = lpos; sn[warp] = lneg; sc[warp] = lcnt; }
    __syncthreads();

    if (threadIdx.x == 0) {
        float tp = 0.0f, tn = 0.0f;  int tc = 0;
        #pragma unroll
        for (int w = 0; w < 8; w++) { tp += sp[w]; tn += sn[w]; tc += sc[w]; }
        g_pos[blockIdx.x] = tp;
        g_neg[blockIdx.x] = tn;
        g_cnt[blockIdx.x] = tc;
    }
}

__global__ void __launch_bounds__(NBLOCKS)
finalize_kernel(float* out, long long total) {
    // One block of NBLOCKS threads: thread i owns slot i.
    double p = (double)g_pos[threadIdx.x];
    double n = (double)g_neg[threadIdx.x];
    long long c = (long long)g_cnt[threadIdx.x];

    #pragma unroll
    for (int o = 16; o > 0; o >>= 1) {
        p += __shfl_down_sync(0xFFFFFFFFu, p, o);
        n += __shfl_down_sync(0xFFFFFFFFu, n, o);
        c += __shfl_down_sync(0xFFFFFFFFu, c, o);
    }

    __shared__ double spd[32];
    __shared__ double snd[32];
    __shared__ long long scd[32];
    int warp = threadIdx.x >> 5;
    int nwarps = (NBLOCKS + 31) / 32;
    if ((threadIdx.x & 31) == 0) { spd[warp] = p; snd[warp] = n; scd[warp] = c; }
    __syncthreads();

    if (threadIdx.x == 0) {
        double tp = 0.0, tn = 0.0;  long long tc = 0;
        for (int w = 0; w < nwarps; w++) { tp += spd[w]; tn += snd[w]; tc += scd[w]; }
        double npos = (double)tc;
        double nneg = (double)total - npos;
        out[0] = (float)(tp / npos + tn / nneg);
    }
}

extern "C" void kernel_launch(void* const* d_in, const int* in_sizes, int n_in,
                              void* d_out, int out_size) {
    const float* pred = (const float*)d_in[0];
    const int*   ty   = (const int*)d_in[1];
    float* out = (float*)d_out;

    long long n = (long long)in_sizes[0];   // 8192*8192, divisible by 4
    int n4 = (int)(n / 4);

    reduce_kernel<<<NBLOCKS, NTHREADS>>>((const float4*)pred, (const int4*)ty, n4);
    finalize_kernel<<<1, NBLOCKS>>>(out, n);
}